// round 10
// baseline (speedup 1.0000x reference)
#include <cuda_runtime.h>
#include <math.h>

// Problem constants
#define BATCH   2
#define SEQ     2048
#define DMODEL  1024
#define DKV     256
#define NHEADS  16
#define HKV     4
#define DK      64
#define MROWS   (BATCH*SEQ)   // 4096

// Scratch (allocation-free rule: __device__ globals)
__device__ float g_Q [MROWS*DMODEL];   // 16 MB
__device__ float g_K [MROWS*DKV];      //  4 MB
__device__ float g_V [MROWS*DKV];      //  4 MB
__device__ float g_AO[MROWS*DMODEL];   // 16 MB

// ---------------------------------------------------------------------------
// Packed f32x2 helpers (sm_103a): FFMA2 via PTX fma.rn.f32x2.
// Per-lane IEEE fp32 — results are bitwise identical to scalar FFMA chains.
// ---------------------------------------------------------------------------
typedef unsigned long long u64t;

__device__ __forceinline__ u64t pack_dup(float v) {
    u64t r;
    asm("mov.b64 %0, {%1, %1};" : "=l"(r) : "f"(v));
    return r;
}
__device__ __forceinline__ void fma2(u64t& acc, u64t a, u64t b) {
    asm("fma.rn.f32x2 %0, %1, %2, %0;" : "+l"(acc) : "l"(a), "l"(b));
}
__device__ __forceinline__ void mul2(u64t& acc, u64t s) {
    asm("mul.rn.f32x2 %0, %1, %2;" : "=l"(acc) : "l"(acc), "l"(s));
}
__device__ __forceinline__ float2 unpack2(u64t v) {
    float lo, hi;
    asm("mov.b64 {%0, %1}, %2;" : "=f"(lo), "=f"(hi) : "l"(v));
    return make_float2(lo, hi);
}

// ---------------------------------------------------------------------------
// GEMM: C[M,N] = A[M,K] * B[N,K]^T + bias[N]
// Requires M%64==0, N%64==0, K%16==0 (true for all call sites here).
// 64x64x16 tiles, 256 threads, 4x4 register micro-tile per thread (f32x2).
// ---------------------------------------------------------------------------
__global__ __launch_bounds__(256) void gemm_nt(const float* __restrict__ A,
                                               const float* __restrict__ B,
                                               const float* __restrict__ bias,
                                               float* __restrict__ C,
                                               int M, int N, int K)
{
    __shared__ __align__(16) float As[16 * 68];  // As[k][m] transposed
    __shared__ __align__(16) float Bs[16 * 68];  // Bs[k][n] transposed

    const int tid = threadIdx.x;
    const int tx  = tid & 15;        // 0..15 -> N dim
    const int ty  = tid >> 4;        // 0..15 -> M dim
    const int m0  = blockIdx.y * 64;
    const int n0  = blockIdx.x * 64;

    const int lrow = tid >> 2;       // 0..63
    const int lc4  = tid & 3;        // 0..3 (float4 index within 16-wide k tile)
    const float* Aptr = A + (size_t)(m0 + lrow) * K + lc4 * 4;
    const float* Bptr = B + (size_t)(n0 + lrow) * K + lc4 * 4;

    const float* Abase = &As[ty * 4];   // 16B aligned (ty*16 bytes)
    const float* Bbase = &Bs[tx * 4];

    // acc2[i][p]: packed pair {C[i][2p], C[i][2p+1]}
    u64t acc2[4][2] = {};

    for (int k0 = 0; k0 < K; k0 += 16) {
        float4 av = *(const float4*)(Aptr + k0);
        float4 bv = *(const float4*)(Bptr + k0);
        __syncthreads();
        As[(lc4*4+0)*68 + lrow] = av.x;
        As[(lc4*4+1)*68 + lrow] = av.y;
        As[(lc4*4+2)*68 + lrow] = av.z;
        As[(lc4*4+3)*68 + lrow] = av.w;
        Bs[(lc4*4+0)*68 + lrow] = bv.x;
        Bs[(lc4*4+1)*68 + lrow] = bv.y;
        Bs[(lc4*4+2)*68 + lrow] = bv.z;
        Bs[(lc4*4+3)*68 + lrow] = bv.w;
        __syncthreads();
        #pragma unroll
        for (int kk = 0; kk < 16; kk++) {
            float4     a  = *(const float4*)(Abase + kk*68);
            ulonglong2 b2 = *(const ulonglong2*)(Bbase + kk*68); // {b.x,b.y},{b.z,b.w}
            u64t a0 = pack_dup(a.x), a1 = pack_dup(a.y),
                 a2 = pack_dup(a.z), a3 = pack_dup(a.w);
            fma2(acc2[0][0], a0, b2.x); fma2(acc2[0][1], a0, b2.y);
            fma2(acc2[1][0], a1, b2.x); fma2(acc2[1][1], a1, b2.y);
            fma2(acc2[2][0], a2, b2.x); fma2(acc2[2][1], a2, b2.y);
            fma2(acc2[3][0], a3, b2.x); fma2(acc2[3][1], a3, b2.y);
        }
    }

    const float4 bv = *(const float4*)(bias + n0 + tx*4);
    #pragma unroll
    for (int i = 0; i < 4; i++) {
        float2 c01 = unpack2(acc2[i][0]);
        float2 c23 = unpack2(acc2[i][1]);
        float4 ov;
        ov.x = c01.x + bv.x;
        ov.y = c01.y + bv.y;
        ov.z = c23.x + bv.z;
        ov.w = c23.y + bv.w;
        *(float4*)(C + (size_t)(m0 + ty*4 + i) * N + n0 + tx*4) = ov;
    }
}

// ---------------------------------------------------------------------------
// Flash attention: grid (32 q-tiles, 16 heads, 2 batches), 256 threads.
// Each CTA: 64 query rows x all 2048 keys (in 32 tiles of 64), d_k = 64.
// Online softmax, fp32 throughout (FFMA2 inner loops). 68 KB dynamic smem.
// ---------------------------------------------------------------------------
#define ATTN_SMEM (4 * 64 * 68 * (int)sizeof(float))

__global__ __launch_bounds__(256) void attn_kernel()
{
    extern __shared__ __align__(16) float sm[];
    float* Qs = sm;               // Qs[d*68 + r]   (transposed)
    float* Ks = sm + 64*68;       // Ks[d*68 + c]   (transposed)
    float* Vs = sm + 2*64*68;     // Vs[c*68 + d]   (natural)
    float* Ps = sm + 3*64*68;     // Ps[c*68 + r]   (transposed)

    const int tid  = threadIdx.x;
    const int tx   = tid & 15;    // key-col / out-dim group
    const int ty   = tid >> 4;    // query-row group
    const int q0   = blockIdx.x * 64;
    const int head = blockIdx.y;
    const int b    = blockIdx.z;
    const int hkv  = head >> 2;

    const float* Qg = g_Q + (size_t)b * SEQ * DMODEL + head * DK;
    const float* Kg = g_K + (size_t)b * SEQ * DKV    + hkv  * DK;
    const float* Vg = g_V + (size_t)b * SEQ * DKV    + hkv  * DK;

    // Load Q tile (scaled by 1/sqrt(64)), transposed into smem
    const float scale = 0.125f;
    #pragma unroll
    for (int u = 0; u < 4; u++) {
        int idx = u * 256 + tid;
        int r   = idx >> 4;      // 0..63
        int c4  = idx & 15;      // 0..15
        float4 v = *(const float4*)(Qg + (size_t)(q0 + r) * DMODEL + c4*4);
        Qs[(c4*4+0)*68 + r] = v.x * scale;
        Qs[(c4*4+1)*68 + r] = v.y * scale;
        Qs[(c4*4+2)*68 + r] = v.z * scale;
        Qs[(c4*4+3)*68 + r] = v.w * scale;
    }

    // o2[i][p]: packed pair {O[i][2p], O[i][2p+1]}; 0ull == {0.0f, 0.0f}
    u64t o2[4][2] = {};
    float m[4], l[4];
    #pragma unroll
    for (int i = 0; i < 4; i++) { m[i] = -INFINITY; l[i] = 0.0f; }

    const float* Qbase = &Qs[ty * 4];
    const float* Kbase = &Ks[tx * 4];
    const float* Pbase = &Ps[ty * 4];
    const float* Vbase = &Vs[tx * 4];

    for (int kt = 0; kt < SEQ / 64; kt++) {
        const int c0 = kt * 64;
        __syncthreads();   // previous Ps/Vs reads done (also covers Q store, iter 0)
        #pragma unroll
        for (int u = 0; u < 4; u++) {
            int idx = u * 256 + tid;
            int r   = idx >> 4;
            int c4  = idx & 15;
            float4 kv = *(const float4*)(Kg + (size_t)(c0 + r) * DKV + c4*4);
            Ks[(c4*4+0)*68 + r] = kv.x;
            Ks[(c4*4+1)*68 + r] = kv.y;
            Ks[(c4*4+2)*68 + r] = kv.z;
            Ks[(c4*4+3)*68 + r] = kv.w;
            float4 vv = *(const float4*)(Vg + (size_t)(c0 + r) * DKV + c4*4);
            *(float4*)&Vs[r*68 + c4*4] = vv;
        }
        __syncthreads();

        // S = (Q*scale) @ K^T  -> 4x4 per thread, packed pairs along key dim
        u64t s2[4][2] = {};
        #pragma unroll 8
        for (int k = 0; k < 64; k++) {
            float4     a  = *(const float4*)(Qbase + k*68);
            ulonglong2 b2 = *(const ulonglong2*)(Kbase + k*68);
            u64t a0 = pack_dup(a.x), a1 = pack_dup(a.y),
                 a2 = pack_dup(a.z), a3 = pack_dup(a.w);
            fma2(s2[0][0], a0, b2.x); fma2(s2[0][1], a0, b2.y);
            fma2(s2[1][0], a1, b2.x); fma2(s2[1][1], a1, b2.y);
            fma2(s2[2][0], a2, b2.x); fma2(s2[2][1], a2, b2.y);
            fma2(s2[3][0], a3, b2.x); fma2(s2[3][1], a3, b2.y);
        }
        float s[4][4];
        #pragma unroll
        for (int i = 0; i < 4; i++) {
            float2 p01 = unpack2(s2[i][0]);
            float2 p23 = unpack2(s2[i][1]);
            s[i][0] = p01.x; s[i][1] = p01.y; s[i][2] = p23.x; s[i][3] = p23.y;
        }

        // Online softmax per query row (16 lanes with same ty share a row group)
        #pragma unroll
        for (int i = 0; i < 4; i++) {
            float mm = fmaxf(fmaxf(s[i][0], s[i][1]), fmaxf(s[i][2], s[i][3]));
            mm = fmaxf(mm, __shfl_xor_sync(0xffffffffu, mm, 1, 16));
            mm = fmaxf(mm, __shfl_xor_sync(0xffffffffu, mm, 2, 16));
            mm = fmaxf(mm, __shfl_xor_sync(0xffffffffu, mm, 4, 16));
            mm = fmaxf(mm, __shfl_xor_sync(0xffffffffu, mm, 8, 16));
            float mn   = fmaxf(m[i], mm);
            float corr = __expf(m[i] - mn);
            m[i] = mn;
            float sum = 0.0f;
            #pragma unroll
            for (int j = 0; j < 4; j++) {
                s[i][j] = __expf(s[i][j] - mn);
                sum += s[i][j];
            }
            sum += __shfl_xor_sync(0xffffffffu, sum, 1, 16);
            sum += __shfl_xor_sync(0xffffffffu, sum, 2, 16);
            sum += __shfl_xor_sync(0xffffffffu, sum, 4, 16);
            sum += __shfl_xor_sync(0xffffffffu, sum, 8, 16);
            l[i] = l[i] * corr + sum;
            u64t corrd = pack_dup(corr);
            mul2(o2[i][0], corrd);
            mul2(o2[i][1], corrd);
        }

        // Stash P transposed for the PV GEMM.
        // For fixed j the four dests Ps[(tx*4+j)*68 + ty*4 + i], i=0..3 are
        // contiguous and 16B-aligned (68*4=272=17*16 bytes/row, ty*16 base)
        // -> one STS.128 per j instead of four STS.32. Same values, same
        // addresses; 4x fewer store instructions at unchanged conflict degree.
        #pragma unroll
        for (int j = 0; j < 4; j++) {
            float4 pv = make_float4(s[0][j], s[1][j], s[2][j], s[3][j]);
            *(float4*)&Ps[(tx*4+j)*68 + ty*4] = pv;
        }
        __syncthreads();

        // O += P @ V  (packed pairs along the output-dim)
        #pragma unroll 8
        for (int c = 0; c < 64; c++) {
            float4     p  = *(const float4*)(Pbase + c*68);
            ulonglong2 v2 = *(const ulonglong2*)(Vbase + c*68);
            u64t p0 = pack_dup(p.x), p1 = pack_dup(p.y),
                 p2 = pack_dup(p.z), p3 = pack_dup(p.w);
            fma2(o2[0][0], p0, v2.x); fma2(o2[0][1], p0, v2.y);
            fma2(o2[1][0], p1, v2.x); fma2(o2[1][1], p1, v2.y);
            fma2(o2[2][0], p2, v2.x); fma2(o2[2][1], p2, v2.y);
            fma2(o2[3][0], p3, v2.x); fma2(o2[3][1], p3, v2.y);
        }
    }

    // Normalize and write: AO[b, s, head*64 + d]
    float* AOg = g_AO + (size_t)b * SEQ * DMODEL + head * DK;
    #pragma unroll
    for (int i = 0; i < 4; i++) {
        float inv = 1.0f / l[i];
        float2 o01 = unpack2(o2[i][0]);
        float2 o23 = unpack2(o2[i][1]);
        float4 ov;
        ov.x = o01.x * inv;
        ov.y = o01.y * inv;
        ov.z = o23.x * inv;
        ov.w = o23.y * inv;
        *(float4*)(AOg + (size_t)(q0 + ty*4 + i) * DMODEL + tx*4) = ov;
    }
}

// ---------------------------------------------------------------------------
extern "C" void kernel_launch(void* const* d_in, const int* in_sizes, int n_in,
                              void* d_out, int out_size)
{
    const float* query = (const float*)d_in[0];
    const float* key   = (const float*)d_in[1];
    const float* value = (const float*)d_in[2];
    const float* w_q   = (const float*)d_in[3];
    const float* b_q   = (const float*)d_in[4];
    const float* w_k   = (const float*)d_in[5];
    const float* b_k   = (const float*)d_in[6];
    const float* w_v   = (const float*)d_in[7];
    const float* b_v   = (const float*)d_in[8];
    const float* w_o   = (const float*)d_in[9];
    const float* b_o   = (const float*)d_in[10];
    float* out = (float*)d_out;

    float *Qb, *Kb, *Vb, *AOb;
    cudaGetSymbolAddress((void**)&Qb,  g_Q);
    cudaGetSymbolAddress((void**)&Kb,  g_K);
    cudaGetSymbolAddress((void**)&Vb,  g_V);
    cudaGetSymbolAddress((void**)&AOb, g_AO);

    cudaFuncSetAttribute(attn_kernel,
                         cudaFuncAttributeMaxDynamicSharedMemorySize, ATTN_SMEM);

    dim3 blk(256);
    // Projections
    gemm_nt<<<dim3(DMODEL/64, MROWS/64), blk>>>(query, w_q, b_q, Qb, MROWS, DMODEL, DMODEL);
    gemm_nt<<<dim3(DKV/64,    MROWS/64), blk>>>(key,   w_k, b_k, Kb, MROWS, DKV,    DMODEL);
    gemm_nt<<<dim3(DKV/64,    MROWS/64), blk>>>(value, w_v, b_v, Vb, MROWS, DKV,    DMODEL);
    // Attention
    attn_kernel<<<dim3(SEQ/64, NHEADS, BATCH), blk, ATTN_SMEM>>>();
    // Output projection
    gemm_nt<<<dim3(DMODEL/64, MROWS/64), blk>>>(AOb, w_o, b_o, out, MROWS, DMODEL, DMODEL);
}

// round 11
// speedup vs baseline: 1.0521x; 1.0521x over previous
#include <cuda_runtime.h>
#include <math.h>

// Problem constants
#define BATCH   2
#define SEQ     2048
#define DMODEL  1024
#define DKV     256
#define NHEADS  16
#define HKV     4
#define DK      64
#define MROWS   (BATCH*SEQ)   // 4096

// Scratch (allocation-free rule: __device__ globals)
__device__ float g_Q [MROWS*DMODEL];   // 16 MB
__device__ float g_K [MROWS*DKV];      //  4 MB
__device__ float g_V [MROWS*DKV];      //  4 MB
__device__ float g_AO[MROWS*DMODEL];   // 16 MB

// ---------------------------------------------------------------------------
// Packed f32x2 helpers (sm_103a): FFMA2 via PTX fma.rn.f32x2.
// Per-lane IEEE fp32 — bitwise identical to scalar FFMA chains.
// Packing axis = adjacent output ROWS, so packed 'a' operands load directly
// from consecutive smem floats (no dup); only the broadcast operand is dup'd.
// ---------------------------------------------------------------------------
typedef unsigned long long u64t;

__device__ __forceinline__ u64t pack_dup(float v) {
    u64t r;
    asm("mov.b64 %0, {%1, %1};" : "=l"(r) : "f"(v));
    return r;
}
__device__ __forceinline__ u64t pack2f(float lo, float hi) {
    u64t r;
    asm("mov.b64 %0, {%1, %2};" : "=l"(r) : "f"(lo), "f"(hi));
    return r;
}
__device__ __forceinline__ void fma2(u64t& acc, u64t a, u64t b) {
    asm("fma.rn.f32x2 %0, %1, %2, %0;" : "+l"(acc) : "l"(a), "l"(b));
}
__device__ __forceinline__ void mul2(u64t& acc, u64t s) {
    asm("mul.rn.f32x2 %0, %1, %2;" : "=l"(acc) : "l"(acc), "l"(s));
}
__device__ __forceinline__ float2 unpack2(u64t v) {
    float lo, hi;
    asm("mov.b64 {%0, %1}, %2;" : "=f"(lo), "=f"(hi) : "l"(v));
    return make_float2(lo, hi);
}

// ---------------------------------------------------------------------------
// GEMM: C[M,N] = A[M,K] * B[N,K]^T + bias[N]
// Requires M%128==0, N%64==0, K%16==0 (true for all call sites here).
// 128x64x16 tiles, 256 threads, 8x4 micro-tile per thread (row-pair f32x2).
// ---------------------------------------------------------------------------
__global__ __launch_bounds__(256) void gemm_nt(const float* __restrict__ A,
                                               const float* __restrict__ B,
                                               const float* __restrict__ bias,
                                               float* __restrict__ C,
                                               int M, int N, int K)
{
    __shared__ __align__(16) float As[16 * 132];  // As[k][m], m=0..127 (pad 132)
    __shared__ __align__(16) float Bs[16 * 68];   // Bs[k][n], n=0..63  (pad 68)

    const int tid = threadIdx.x;
    const int tx  = tid & 15;        // 0..15 -> N dim (4 cols each)
    const int ty  = tid >> 4;        // 0..15 -> M dim (8 rows each)
    const int m0  = blockIdx.y * 128;
    const int n0  = blockIdx.x * 64;

    const int lrow = tid >> 2;       // 0..63
    const int lc4  = tid & 3;        // float4 index within 16-wide k tile
    const float* Ap0 = A + (size_t)(m0 + lrow)      * K + lc4 * 4;
    const float* Ap1 = A + (size_t)(m0 + lrow + 64) * K + lc4 * 4;
    const float* Bp  = B + (size_t)(n0 + lrow)      * K + lc4 * 4;

    const float* Abase = &As[ty * 8];   // 32B aligned; row stride 132*4=528B (16B mult)
    const float* Bbase = &Bs[tx * 4];

    // acc2[p][j]: packed row pair {C[2p][j], C[2p+1][j]} of this thread's 8x4 tile
    u64t acc2[4][4] = {};

    for (int k0 = 0; k0 < K; k0 += 16) {
        float4 av0 = *(const float4*)(Ap0 + k0);
        float4 av1 = *(const float4*)(Ap1 + k0);
        float4 bv  = *(const float4*)(Bp  + k0);
        __syncthreads();
        As[(lc4*4+0)*132 + lrow] = av0.x;
        As[(lc4*4+1)*132 + lrow] = av0.y;
        As[(lc4*4+2)*132 + lrow] = av0.z;
        As[(lc4*4+3)*132 + lrow] = av0.w;
        As[(lc4*4+0)*132 + lrow + 64] = av1.x;
        As[(lc4*4+1)*132 + lrow + 64] = av1.y;
        As[(lc4*4+2)*132 + lrow + 64] = av1.z;
        As[(lc4*4+3)*132 + lrow + 64] = av1.w;
        Bs[(lc4*4+0)*68 + lrow] = bv.x;
        Bs[(lc4*4+1)*68 + lrow] = bv.y;
        Bs[(lc4*4+2)*68 + lrow] = bv.z;
        Bs[(lc4*4+3)*68 + lrow] = bv.w;
        __syncthreads();
        #pragma unroll
        for (int kk = 0; kk < 16; kk++) {
            ulonglong2 a01 = *(const ulonglong2*)(Abase + kk*132);      // rows (0,1),(2,3)
            ulonglong2 a23 = *(const ulonglong2*)(Abase + kk*132 + 4);  // rows (4,5),(6,7)
            float4     bq  = *(const float4*)(Bbase + kk*68);
            u64t b0 = pack_dup(bq.x), b1 = pack_dup(bq.y),
                 b2 = pack_dup(bq.z), b3 = pack_dup(bq.w);
            fma2(acc2[0][0], a01.x, b0); fma2(acc2[0][1], a01.x, b1); fma2(acc2[0][2], a01.x, b2); fma2(acc2[0][3], a01.x, b3);
            fma2(acc2[1][0], a01.y, b0); fma2(acc2[1][1], a01.y, b1); fma2(acc2[1][2], a01.y, b2); fma2(acc2[1][3], a01.y, b3);
            fma2(acc2[2][0], a23.x, b0); fma2(acc2[2][1], a23.x, b1); fma2(acc2[2][2], a23.x, b2); fma2(acc2[2][3], a23.x, b3);
            fma2(acc2[3][0], a23.y, b0); fma2(acc2[3][1], a23.y, b1); fma2(acc2[3][2], a23.y, b2); fma2(acc2[3][3], a23.y, b3);
        }
    }

    const float4 bv = *(const float4*)(bias + n0 + tx*4);
    #pragma unroll
    for (int p = 0; p < 4; p++) {
        float2 c0 = unpack2(acc2[p][0]);
        float2 c1 = unpack2(acc2[p][1]);
        float2 c2 = unpack2(acc2[p][2]);
        float2 c3 = unpack2(acc2[p][3]);
        float4 r0 = make_float4(c0.x + bv.x, c1.x + bv.y, c2.x + bv.z, c3.x + bv.w);
        float4 r1 = make_float4(c0.y + bv.x, c1.y + bv.y, c2.y + bv.z, c3.y + bv.w);
        *(float4*)(C + (size_t)(m0 + ty*8 + 2*p    ) * N + n0 + tx*4) = r0;
        *(float4*)(C + (size_t)(m0 + ty*8 + 2*p + 1) * N + n0 + tx*4) = r1;
    }
}

// ---------------------------------------------------------------------------
// Flash attention: grid (16 q-tiles, 16 heads, 2 batches), 256 threads.
// Each CTA: 128 query rows x all 2048 keys (32 tiles of 64), d_k = 64.
// 8x4 micro-tile per thread (row-pair f32x2). 100 KB dynamic smem, 2 CTA/SM.
// ---------------------------------------------------------------------------
#define ATTN_SMEM ((2*64*132 + 2*64*68) * (int)sizeof(float))   // 102400 B

__global__ __launch_bounds__(256, 2) void attn_kernel()
{
    extern __shared__ __align__(16) float sm[];
    float* Qs = sm;                        // Qs[d*132 + r]  (transposed, r=0..127)
    float* Ks = sm + 64*132;               // Ks[d*68 + c]   (transposed)
    float* Vs = sm + 64*132 + 64*68;       // Vs[c*68 + d]   (natural)
    float* Ps = sm + 64*132 + 2*64*68;     // Ps[c*132 + r]  (transposed)

    const int tid  = threadIdx.x;
    const int tx   = tid & 15;    // key-col / out-dim group (4 each)
    const int ty   = tid >> 4;    // query-row group (8 each)
    const int q0   = blockIdx.x * 128;
    const int head = blockIdx.y;
    const int bz   = blockIdx.z;
    const int hkv  = head >> 2;

    const float* Qg = g_Q + (size_t)bz * SEQ * DMODEL + head * DK;
    const float* Kg = g_K + (size_t)bz * SEQ * DKV    + hkv  * DK;
    const float* Vg = g_V + (size_t)bz * SEQ * DKV    + hkv  * DK;

    // Load Q tile (scaled by 1/sqrt(64)), transposed into smem
    const float scale = 0.125f;
    #pragma unroll
    for (int u = 0; u < 8; u++) {
        int idx = u * 256 + tid;
        int r   = idx >> 4;      // 0..127
        int c4  = idx & 15;      // 0..15
        float4 v = *(const float4*)(Qg + (size_t)(q0 + r) * DMODEL + c4*4);
        Qs[(c4*4+0)*132 + r] = v.x * scale;
        Qs[(c4*4+1)*132 + r] = v.y * scale;
        Qs[(c4*4+2)*132 + r] = v.z * scale;
        Qs[(c4*4+3)*132 + r] = v.w * scale;
    }

    // o2[p][d]: packed row pair {O[2p][d], O[2p+1][d]} of this thread's 8x4 tile
    u64t o2[4][4] = {};
    float m[8], l[8];
    #pragma unroll
    for (int i = 0; i < 8; i++) { m[i] = -INFINITY; l[i] = 0.0f; }

    const float* Qbase = &Qs[ty * 8];   // 32B aligned; row stride 528B
    const float* Kbase = &Ks[tx * 4];
    const float* Pbase = &Ps[ty * 8];
    const float* Vbase = &Vs[tx * 4];

    for (int kt = 0; kt < SEQ / 64; kt++) {
        const int c0 = kt * 64;
        __syncthreads();   // previous Ps/Vs reads done (also covers Q store, iter 0)
        #pragma unroll
        for (int u = 0; u < 4; u++) {
            int idx = u * 256 + tid;
            int r   = idx >> 4;      // 0..63
            int c4  = idx & 15;
            float4 kv = *(const float4*)(Kg + (size_t)(c0 + r) * DKV + c4*4);
            Ks[(c4*4+0)*68 + r] = kv.x;
            Ks[(c4*4+1)*68 + r] = kv.y;
            Ks[(c4*4+2)*68 + r] = kv.z;
            Ks[(c4*4+3)*68 + r] = kv.w;
            float4 vv = *(const float4*)(Vg + (size_t)(c0 + r) * DKV + c4*4);
            *(float4*)&Vs[r*68 + c4*4] = vv;
        }
        __syncthreads();

        // S = (Q*scale) @ K^T -> 8x4 per thread, rows packed in pairs
        u64t s2[4][4] = {};
        #pragma unroll 4
        for (int k = 0; k < 64; k++) {
            ulonglong2 a01 = *(const ulonglong2*)(Qbase + k*132);      // rows (0,1),(2,3)
            ulonglong2 a23 = *(const ulonglong2*)(Qbase + k*132 + 4);  // rows (4,5),(6,7)
            float4     bq  = *(const float4*)(Kbase + k*68);
            u64t b0 = pack_dup(bq.x), b1 = pack_dup(bq.y),
                 b2 = pack_dup(bq.z), b3 = pack_dup(bq.w);
            fma2(s2[0][0], a01.x, b0); fma2(s2[0][1], a01.x, b1); fma2(s2[0][2], a01.x, b2); fma2(s2[0][3], a01.x, b3);
            fma2(s2[1][0], a01.y, b0); fma2(s2[1][1], a01.y, b1); fma2(s2[1][2], a01.y, b2); fma2(s2[1][3], a01.y, b3);
            fma2(s2[2][0], a23.x, b0); fma2(s2[2][1], a23.x, b1); fma2(s2[2][2], a23.x, b2); fma2(s2[2][3], a23.x, b3);
            fma2(s2[3][0], a23.y, b0); fma2(s2[3][1], a23.y, b1); fma2(s2[3][2], a23.y, b2); fma2(s2[3][3], a23.y, b3);
        }
        float s[8][4];
        #pragma unroll
        for (int p = 0; p < 4; p++)
            #pragma unroll
            for (int j = 0; j < 4; j++) {
                float2 v = unpack2(s2[p][j]);
                s[2*p  ][j] = v.x;
                s[2*p+1][j] = v.y;
            }

        // Online softmax per query row (16 lanes with same ty share a row group)
        float corr[8];
        #pragma unroll
        for (int i = 0; i < 8; i++) {
            float mm = fmaxf(fmaxf(s[i][0], s[i][1]), fmaxf(s[i][2], s[i][3]));
            mm = fmaxf(mm, __shfl_xor_sync(0xffffffffu, mm, 1, 16));
            mm = fmaxf(mm, __shfl_xor_sync(0xffffffffu, mm, 2, 16));
            mm = fmaxf(mm, __shfl_xor_sync(0xffffffffu, mm, 4, 16));
            mm = fmaxf(mm, __shfl_xor_sync(0xffffffffu, mm, 8, 16));
            float mn = fmaxf(m[i], mm);
            corr[i]  = __expf(m[i] - mn);
            m[i] = mn;
            float sum = 0.0f;
            #pragma unroll
            for (int j = 0; j < 4; j++) {
                s[i][j] = __expf(s[i][j] - mn);
                sum += s[i][j];
            }
            sum += __shfl_xor_sync(0xffffffffu, sum, 1, 16);
            sum += __shfl_xor_sync(0xffffffffu, sum, 2, 16);
            sum += __shfl_xor_sync(0xffffffffu, sum, 4, 16);
            sum += __shfl_xor_sync(0xffffffffu, sum, 8, 16);
            l[i] = l[i] * corr[i] + sum;
        }
        #pragma unroll
        for (int p = 0; p < 4; p++) {
            u64t c2 = pack2f(corr[2*p], corr[2*p+1]);
            mul2(o2[p][0], c2); mul2(o2[p][1], c2);
            mul2(o2[p][2], c2); mul2(o2[p][3], c2);
        }

        // Stash P transposed for the PV GEMM (two STS.128 per j; 16B-aligned:
        // 132*4=528B row stride, ty*32B base).
        #pragma unroll
        for (int j = 0; j < 4; j++) {
            *(float4*)&Ps[(tx*4+j)*132 + ty*8    ] = make_float4(s[0][j], s[1][j], s[2][j], s[3][j]);
            *(float4*)&Ps[(tx*4+j)*132 + ty*8 + 4] = make_float4(s[4][j], s[5][j], s[6][j], s[7][j]);
        }
        __syncthreads();

        // O += P @ V (rows packed in pairs; V broadcast dup'd per out-dim)
        #pragma unroll 4
        for (int c = 0; c < 64; c++) {
            ulonglong2 p01 = *(const ulonglong2*)(Pbase + c*132);
            ulonglong2 p23 = *(const ulonglong2*)(Pbase + c*132 + 4);
            float4     vv  = *(const float4*)(Vbase + c*68);
            u64t v0 = pack_dup(vv.x), v1 = pack_dup(vv.y),
                 v2 = pack_dup(vv.z), v3 = pack_dup(vv.w);
            fma2(o2[0][0], p01.x, v0); fma2(o2[0][1], p01.x, v1); fma2(o2[0][2], p01.x, v2); fma2(o2[0][3], p01.x, v3);
            fma2(o2[1][0], p01.y, v0); fma2(o2[1][1], p01.y, v1); fma2(o2[1][2], p01.y, v2); fma2(o2[1][3], p01.y, v3);
            fma2(o2[2][0], p23.x, v0); fma2(o2[2][1], p23.x, v1); fma2(o2[2][2], p23.x, v2); fma2(o2[2][3], p23.x, v3);
            fma2(o2[3][0], p23.y, v0); fma2(o2[3][1], p23.y, v1); fma2(o2[3][2], p23.y, v2); fma2(o2[3][3], p23.y, v3);
        }
    }

    // Normalize and write: AO[b, s, head*64 + d]
    float* AOg = g_AO + (size_t)bz * SEQ * DMODEL + head * DK;
    #pragma unroll
    for (int p = 0; p < 4; p++) {
        float2 e0 = unpack2(o2[p][0]);
        float2 e1 = unpack2(o2[p][1]);
        float2 e2 = unpack2(o2[p][2]);
        float2 e3 = unpack2(o2[p][3]);
        float inv0 = 1.0f / l[2*p];
        float inv1 = 1.0f / l[2*p+1];
        float4 r0 = make_float4(e0.x*inv0, e1.x*inv0, e2.x*inv0, e3.x*inv0);
        float4 r1 = make_float4(e0.y*inv1, e1.y*inv1, e2.y*inv1, e3.y*inv1);
        *(float4*)(AOg + (size_t)(q0 + ty*8 + 2*p    ) * DMODEL + tx*4) = r0;
        *(float4*)(AOg + (size_t)(q0 + ty*8 + 2*p + 1) * DMODEL + tx*4) = r1;
    }
}

// ---------------------------------------------------------------------------
extern "C" void kernel_launch(void* const* d_in, const int* in_sizes, int n_in,
                              void* d_out, int out_size)
{
    const float* query = (const float*)d_in[0];
    const float* key   = (const float*)d_in[1];
    const float* value = (const float*)d_in[2];
    const float* w_q   = (const float*)d_in[3];
    const float* b_q   = (const float*)d_in[4];
    const float* w_k   = (const float*)d_in[5];
    const float* b_k   = (const float*)d_in[6];
    const float* w_v   = (const float*)d_in[7];
    const float* b_v   = (const float*)d_in[8];
    const float* w_o   = (const float*)d_in[9];
    const float* b_o   = (const float*)d_in[10];
    float* out = (float*)d_out;

    float *Qb, *Kb, *Vb, *AOb;
    cudaGetSymbolAddress((void**)&Qb,  g_Q);
    cudaGetSymbolAddress((void**)&Kb,  g_K);
    cudaGetSymbolAddress((void**)&Vb,  g_V);
    cudaGetSymbolAddress((void**)&AOb, g_AO);

    cudaFuncSetAttribute(attn_kernel,
                         cudaFuncAttributeMaxDynamicSharedMemorySize, ATTN_SMEM);

    dim3 blk(256);
    // Projections (128x64 tiles)
    gemm_nt<<<dim3(DMODEL/64, MROWS/128), blk>>>(query, w_q, b_q, Qb, MROWS, DMODEL, DMODEL);
    gemm_nt<<<dim3(DKV/64,    MROWS/128), blk>>>(key,   w_k, b_k, Kb, MROWS, DKV,    DMODEL);
    gemm_nt<<<dim3(DKV/64,    MROWS/128), blk>>>(value, w_v, b_v, Vb, MROWS, DKV,    DMODEL);
    // Attention (128-query tiles)
    attn_kernel<<<dim3(SEQ/128, NHEADS, BATCH), blk, ATTN_SMEM>>>();
    // Output projection
    gemm_nt<<<dim3(DMODEL/64, MROWS/128), blk>>>(AOb, w_o, b_o, out, MROWS, DMODEL, DMODEL);
}